// round 1
// baseline (speedup 1.0000x reference)
#include <cuda_runtime.h>
#include <cstdint>
#include <math_constants.h>

#define TT 1024
#define BB 128
#define LL 128

// ---- scratch (no allocations allowed) ----
__device__ float g_PM[TT * BB];   // per (t,b) max_j predictions
__device__ float g_numer[BB];
__device__ float g_denom[BB];
__device__ int   g_len[BB];

// mask dtype is unknown (bool8 vs wider). Detect: byte[1] nonzero iff 1-byte mask
// (mask[0,1] is always true since lengths >= T/2). The int path's nonzero test
// also correctly handles int32 and float32 encodings of 0/1.
__device__ __forceinline__ int mask_val(const uint8_t* m, int idx, bool is8) {
    return is8 ? (m[idx] != 0) : (((const int*)m)[idx] != 0);
}

// ============================================================
// Kernel 1: PM[t,b] = max_j predictions[t,b,j]   (HBM-bound prepass)
// one warp per row, 8 warps per block
// ============================================================
__global__ void rowmax_kernel(const float* __restrict__ pred) {
    int row  = blockIdx.x * 8 + (threadIdx.x >> 5);
    int lane = threadIdx.x & 31;
    float4 p = __ldg((const float4*)(pred + (size_t)row * LL + lane * 4));
    float m = fmaxf(fmaxf(p.x, p.y), fmaxf(p.z, p.w));
    #pragma unroll
    for (int o = 16; o; o >>= 1) m = fmaxf(m, __shfl_xor_sync(0xffffffffu, m, o));
    if (lane == 0) g_PM[row] = m;
}

// ============================================================
// Kernel 2: numerator + sequence lengths (one block per batch)
// ============================================================
__global__ void numer_kernel(const float* __restrict__ pred,
                             const int*   __restrict__ tgt,
                             const uint8_t* __restrict__ mask,
                             const float* __restrict__ trans,
                             const float* __restrict__ start,
                             const float* __restrict__ endsc) {
    int b = blockIdx.x, k = threadIdx.x;
    bool is8 = (mask[1] != 0);
    float part = 0.f;
    int cnt = 0;
    for (int t = k; t < TT; t += 128) {
        int mv = mask_val(mask, t * BB + b, is8);
        cnt += mv;
        if (t == 0) {
            int y0 = tgt[b];
            part += start[y0] + pred[(size_t)b * LL + y0];
        } else if (mv) {
            int yp = tgt[(t - 1) * BB + b];
            int y  = tgt[t * BB + b];
            part += trans[yp * LL + y] + pred[((size_t)t * BB + b) * LL + y];
        }
    }
    __shared__ float sred[4];
    __shared__ int   cred[4];
    #pragma unroll
    for (int o = 16; o; o >>= 1) {
        part += __shfl_xor_sync(0xffffffffu, part, o);
        cnt  += __shfl_xor_sync(0xffffffffu, cnt, o);
    }
    if ((k & 31) == 0) { sred[k >> 5] = part; cred[k >> 5] = cnt; }
    __syncthreads();
    if (k == 0) {
        float tot = sred[0] + sred[1] + sred[2] + sred[3];
        int   len = cred[0] + cred[1] + cred[2] + cred[3];
        g_len[b] = len;
        int ylast = tgt[(len - 1) * BB + b];
        g_numer[b] = tot + endsc[ylast];
    }
}

// ============================================================
// block-wide reductions over 128 threads
// ============================================================
__device__ __forceinline__ float block_max128(float v, float* red) {
    #pragma unroll
    for (int o = 16; o; o >>= 1) v = fmaxf(v, __shfl_xor_sync(0xffffffffu, v, o));
    if ((threadIdx.x & 31) == 0) red[threadIdx.x >> 5] = v;
    __syncthreads();
    v = fmaxf(fmaxf(red[0], red[1]), fmaxf(red[2], red[3]));
    __syncthreads();
    return v;
}
__device__ __forceinline__ float block_sum128(float v, float* red) {
    #pragma unroll
    for (int o = 16; o; o >>= 1) v += __shfl_xor_sync(0xffffffffu, v, o);
    if ((threadIdx.x & 31) == 0) red[threadIdx.x >> 5] = v;
    __syncthreads();
    v = red[0] + red[1] + red[2] + red[3];
    __syncthreads();
    return v;
}

// ============================================================
// Kernel 3: the forward-algorithm scan, one block per batch.
// Thread j owns column E[:,j] = exp(trans[:,j] - ctmax[j]) in 128 registers.
// alpha kept as (C, u[j]) with alpha = C + log(u); per step:
//   s[j]  = sum_i u[i] * E[i][j]                     (pure FFMA matvec)
//   u'[j] = s[j] * exp(pred[t,b,j] + ctmax[j] - PM[t,b]);  C += PM[t,b]
// exact-max renorm of u every 8 steps keeps everything in float range.
// ============================================================
__global__ void __launch_bounds__(128, 1)
scan_kernel(const float* __restrict__ pred,
            const float* __restrict__ trans,
            const float* __restrict__ start,
            const float* __restrict__ endsc) {
    int b = blockIdx.x, j = threadIdx.x;
    __shared__ __align__(16) float ub[2][LL];
    __shared__ float red[4];

    // ---- prologue: E column in registers (coalesced loads over i) ----
    float E[LL];
    float ctm = -CUDART_INF_F;
    #pragma unroll
    for (int i = 0; i < LL; i++) {
        float v = __ldg(trans + i * LL + j);
        E[i] = v;
        ctm = fmaxf(ctm, v);
    }
    #pragma unroll
    for (int i = 0; i < LL; i++) E[i] = expf(E[i] - ctm);   // accurate exp, one-time

    int len = g_len[b];

    // ---- init: alpha0 = start + pred[0] ----
    float g0 = start[j] + __ldg(pred + (size_t)b * LL + j);
    float m0 = block_max128(g0, red);
    float C = m0;
    ub[0][j] = __expf(g0 - m0);

    // ---- distance-2 prefetch pipeline for pred row + PM scalar ----
    int ta = (1 < len) ? 1 : len - 1;
    int tb2 = (2 < len) ? 2 : len - 1;
    float pr0 = __ldg(pred + ((size_t)ta  * BB + b) * LL + j);
    float pm0 = __ldg(g_PM + ta  * BB + b);
    float pr1 = __ldg(pred + ((size_t)tb2 * BB + b) * LL + j);
    float pm1 = __ldg(g_PM + tb2 * BB + b);
    __syncthreads();

    int p = 0;
    for (int t = 1; t < len; t++) {
        float pr = pr0, pm = pm0;
        pr0 = pr1; pm0 = pm1;
        int tf = (t + 2 < len) ? (t + 2) : (len - 1);
        pr1 = __ldg(pred + ((size_t)tf * BB + b) * LL + j);
        pm1 = __ldg(g_PM + tf * BB + b);

        // matvec: s[j] = sum_i u[i] * E[i][j]
        const float4* u4 = (const float4*)ub[p];
        float a0 = 0.f, a1 = 0.f, a2 = 0.f, a3 = 0.f;
        #pragma unroll
        for (int i4 = 0; i4 < LL / 4; i4++) {
            float4 uu = u4[i4];
            a0 = fmaf(E[4 * i4 + 0], uu.x, a0);
            a1 = fmaf(E[4 * i4 + 1], uu.y, a1);
            a2 = fmaf(E[4 * i4 + 2], uu.z, a2);
            a3 = fmaf(E[4 * i4 + 3], uu.w, a3);
        }
        float s = (a0 + a1) + (a2 + a3);

        float v = s * __expf(pr + ctm - pm);
        C += pm;

        if ((t & 7) == 0) {                  // periodic exact renorm
            float mx = block_max128(v, red);
            v = __fdividef(v, mx);
            C += logf(mx);
        }

        p ^= 1;
        ub[p][j] = v;
        __syncthreads();
    }

    // ---- denominator: C + log(sum_j u[j] * exp(end[j])) ----
    float uf = ub[p][j];
    float z = uf * __expf(__ldg(endsc + j));
    float ssum = block_sum128(z, red);
    if (j == 0) g_denom[b] = C + logf(ssum);
}

// ============================================================
// Kernel 4: loss = mean_b(denom - numer)
// ============================================================
__global__ void finalize_kernel(float* out) {
    int b = threadIdx.x;
    float v = g_denom[b] - g_numer[b];
    __shared__ float red[4];
    #pragma unroll
    for (int o = 16; o; o >>= 1) v += __shfl_xor_sync(0xffffffffu, v, o);
    if ((b & 31) == 0) red[b >> 5] = v;
    __syncthreads();
    if (b == 0) out[0] = (red[0] + red[1] + red[2] + red[3]) * (1.0f / BB);
}

// ============================================================
extern "C" void kernel_launch(void* const* d_in, const int* in_sizes, int n_in,
                              void* d_out, int out_size) {
    const float*   pred  = (const float*)d_in[0];
    const int*     tgt   = (const int*)d_in[1];
    const uint8_t* mask  = (const uint8_t*)d_in[2];
    const float*   trans = (const float*)d_in[3];
    const float*   start = (const float*)d_in[4];
    const float*   endsc = (const float*)d_in[5];

    rowmax_kernel<<<(TT * BB) / 8, 256>>>(pred);
    numer_kernel<<<BB, 128>>>(pred, tgt, mask, trans, start, endsc);
    scan_kernel<<<BB, 128>>>(pred, trans, start, endsc);
    finalize_kernel<<<1, 128>>>((float*)d_out);
}

// round 2
// speedup vs baseline: 1.2306x; 1.2306x over previous
#include <cuda_runtime.h>
#include <cstdint>
#include <math_constants.h>

#define TT 1024
#define BB 128
#define LL 128

// ---- scratch (no allocations allowed) ----
__device__ float g_res[BB];
__device__ int   g_ctr = 0;

// named barrier over the 128 scan threads only (warp 4 never participates)
#define BAR1() asm volatile("bar.sync 1, 128;" ::: "memory")

// Blackwell packed fp32 FMA (2 FMAs per instruction) — PTX-only pattern
#define FMA2(d, a, b, c) \
    asm("fma.rn.f32x2 %0, %1, %2, %3;" : "=l"(d) : "l"(a), "l"(b), "l"(c))

// mask dtype unknown (bool8 vs int32/float32): byte[1] nonzero iff 1-byte mask
// (mask[0,1] is always true since lengths >= T/2).
__device__ __forceinline__ int mval(const uint8_t* m, int t, int b, bool is8) {
    size_t idx = (size_t)t * BB + b;
    return is8 ? (m[idx] != 0) : (((const int*)m)[idx] != 0);
}

// ============================================================
// One fused kernel. Block b handles batch b.
//   warps 0-3 (tid 0..127): forward-algorithm scan in scaled-linear domain.
//     thread j owns E[:,j] = exp(trans[:,j] - ctm_j) as 64 packed f32x2 regs.
//     per step: s[j] = sum_i u[i]*E[i][j]  (64 FMA2),  v[j] = s[j]*exp(pr_j+ctm_j-lmx)
//     deferred renorm: every 4 steps measure warp maxes (shfl, no barrier),
//     next step fold -log(max) into the multiplier and C += log(max).
//   warp 4 (tid 128..159): len via ballot binary search + numerator, concurrent.
//   last block reduces g_res -> out (mean).
// ============================================================
__global__ void __launch_bounds__(160, 1)
crf_fused(const float* __restrict__ pred, const int* __restrict__ tgt,
          const uint8_t* __restrict__ mask, const float* __restrict__ trans,
          const float* __restrict__ start, const float* __restrict__ endsc,
          float* __restrict__ out) {
    int b = blockIdx.x;
    int tid = threadIdx.x;

    __shared__ __align__(16) float ub[2][LL];
    __shared__ float red[4];
    __shared__ float smaxs[4];
    __shared__ float s_den, s_num;
    __shared__ int s_len, s_last;

    unsigned long long E2[LL / 2];
    float ctm = -CUDART_INF_F;

    if (tid < LL) {
        int j = tid;
        // pass 1: column max (coalesced over j for each i)
        #pragma unroll
        for (int i = 0; i < LL; i++) ctm = fmaxf(ctm, __ldg(trans + i * LL + j));
        // pass 2 (L1 hits): exp + pack into f32x2 pairs
        #pragma unroll
        for (int m = 0; m < LL / 2; m++) {
            float lo = __expf(__ldg(trans + (2 * m)     * LL + j) - ctm);
            float hi = __expf(__ldg(trans + (2 * m + 1) * LL + j) - ctm);
            unsigned long long pk;
            asm("mov.b64 %0, {%1, %2};" : "=l"(pk) : "f"(lo), "f"(hi));
            E2[m] = pk;
        }
    } else {
        // warp 4: length via 2-round ballot search on the monotone mask column
        int lane = tid - 128;
        bool is8 = (mask[1] != 0);
        unsigned b1 = __ballot_sync(0xffffffffu, mval(mask, lane * 32, b, is8));
        int lmax = 31 - __clz(b1);
        int base = lmax * 32;
        unsigned b2 = __ballot_sync(0xffffffffu, mval(mask, base + lane, b, is8));
        if (lane == 0) s_len = base + __popc(b2);
    }
    __syncthreads();   // #1: s_len visible
    int len = s_len;

    if (tid < LL) {
        int j = tid;
        // ---- init: alpha0 = start + pred[0]; normalize once exactly ----
        float g0 = __ldg(start + j) + __ldg(pred + (size_t)b * LL + j);
        float m = g0;
        #pragma unroll
        for (int o = 16; o; o >>= 1) m = fmaxf(m, __shfl_xor_sync(0xffffffffu, m, o));
        if ((j & 31) == 0) red[j >> 5] = m;
        BAR1();
        float m0 = fmaxf(fmaxf(red[0], red[1]), fmaxf(red[2], red[3]));
        double C = (double)m0;
        ub[0][j] = __expf(g0 - m0);

        // distance-2 prefetch of the pred row
        int ta = (1 < len) ? 1 : 0;
        int tb = (2 < len) ? 2 : len - 1;
        float pr0 = __ldg(pred + ((size_t)ta * BB + b) * LL + j);
        float pr1 = __ldg(pred + ((size_t)tb * BB + b) * LL + j);
        BAR1();   // ub[0] visible to all

        int p = 0;
        for (int t = 1; t < len; t++) {
            float pr = pr0; pr0 = pr1;
            int tf = (t + 2 < len) ? (t + 2) : (len - 1);
            pr1 = __ldg(pred + ((size_t)tf * BB + b) * LL + j);

            float lmx = 0.f;
            if ((t & 3) == 1 && t != 1) {      // fold deferred renorm
                float mx = fmaxf(fmaxf(smaxs[0], smaxs[1]), fmaxf(smaxs[2], smaxs[3]));
                lmx = __logf(mx);
                C += (double)lmx;
            }
            float mult = __expf(pr + ctm - lmx);

            // matvec: s[j] = sum_i u[i] * E[i][j]  (packed, 4 accumulator chains)
            const ulonglong2* u2 = (const ulonglong2*)ub[p];
            unsigned long long a0 = 0ull, a1 = 0ull, a2 = 0ull, a3 = 0ull;
            #pragma unroll
            for (int k = 0; k < 16; k++) {
                ulonglong2 x = u2[2 * k];
                ulonglong2 y = u2[2 * k + 1];
                FMA2(a0, E2[4 * k + 0], x.x, a0);
                FMA2(a1, E2[4 * k + 1], x.y, a1);
                FMA2(a2, E2[4 * k + 2], y.x, a2);
                FMA2(a3, E2[4 * k + 3], y.y, a3);
            }
            float l0, h0, l1, h1, l2, h2, l3, h3;
            asm("mov.b64 {%0,%1}, %2;" : "=f"(l0), "=f"(h0) : "l"(a0));
            asm("mov.b64 {%0,%1}, %2;" : "=f"(l1), "=f"(h1) : "l"(a1));
            asm("mov.b64 {%0,%1}, %2;" : "=f"(l2), "=f"(h2) : "l"(a2));
            asm("mov.b64 {%0,%1}, %2;" : "=f"(l3), "=f"(h3) : "l"(a3));
            float s = ((l0 + h0) + (l1 + h1)) + ((l2 + h2) + (l3 + h3));
            float v = s * mult;

            if ((t & 3) == 0) {               // measure (warp-local, no barrier)
                float mm = v;
                #pragma unroll
                for (int o = 16; o; o >>= 1) mm = fmaxf(mm, __shfl_xor_sync(0xffffffffu, mm, o));
                if ((j & 31) == 0) smaxs[j >> 5] = mm;
            }
            ub[p ^ 1][j] = v;
            p ^= 1;
            BAR1();
        }

        // ---- denominator: C + log(sum_j u[j] * exp(end[j])) ----
        float z = ub[p][j] * __expf(__ldg(endsc + j));
        #pragma unroll
        for (int o = 16; o; o >>= 1) z += __shfl_xor_sync(0xffffffffu, z, o);
        if ((j & 31) == 0) red[j >> 5] = z;
        BAR1();
        if (j == 0) {
            float ssum = red[0] + red[1] + red[2] + red[3];
            s_den = (float)(C + (double)logf(ssum));
        }
    } else {
        // ---- warp 4: numerator (concurrent with the scan) ----
        int lane = tid - 128;
        float part = 0.f;
        #pragma unroll 4
        for (int k = 0; k < 32; k++) {
            int t = k * 32 + lane;
            if (t == 0) {
                int y0 = __ldg(tgt + b);
                part += __ldg(start + y0) + __ldg(pred + (size_t)b * LL + y0);
            } else if (t < len) {
                int y  = __ldg(tgt + t * BB + b);
                int yp = __ldg(tgt + (t - 1) * BB + b);
                part += __ldg(trans + yp * LL + y) + __ldg(pred + ((size_t)t * BB + b) * LL + y);
            }
        }
        #pragma unroll
        for (int o = 16; o; o >>= 1) part += __shfl_xor_sync(0xffffffffu, part, o);
        if (lane == 0) {
            int yl = __ldg(tgt + (len - 1) * BB + b);
            s_num = part + __ldg(endsc + yl);
        }
    }
    __syncthreads();   // #2: s_den, s_num ready

    if (tid == 0) {
        g_res[b] = s_den - s_num;
        __threadfence();
        int c = atomicAdd(&g_ctr, 1);
        s_last = (c == (int)gridDim.x - 1) ? 1 : 0;
    }
    __syncthreads();   // #3

    if (s_last && tid < 32) {
        float v = __ldcg(&g_res[tid])      + __ldcg(&g_res[tid + 32])
                + __ldcg(&g_res[tid + 64]) + __ldcg(&g_res[tid + 96]);
        #pragma unroll
        for (int o = 16; o; o >>= 1) v += __shfl_xor_sync(0xffffffffu, v, o);
        if (tid == 0) { out[0] = v * (1.0f / BB); g_ctr = 0; }
    }
}

// ============================================================
extern "C" void kernel_launch(void* const* d_in, const int* in_sizes, int n_in,
                              void* d_out, int out_size) {
    const float*   pred  = (const float*)d_in[0];
    const int*     tgt   = (const int*)d_in[1];
    const uint8_t* mask  = (const uint8_t*)d_in[2];
    const float*   trans = (const float*)d_in[3];
    const float*   start = (const float*)d_in[4];
    const float*   endsc = (const float*)d_in[5];

    crf_fused<<<BB, 160>>>(pred, tgt, mask, trans, start, endsc, (float*)d_out);
}